// round 16
// baseline (speedup 1.0000x reference)
#include <cuda_runtime.h>
#include <stdint.h>
#include <math.h>

// Problem constants
#define B_  8192
#define T_  128
#define D_  7
#define I_  128
#define C_  10
#define L_  128
#define TD_ 896          // T_*D_
#define LPROW 24         // duplicated leafP row: 10 classes x {v,v} = 20, pad to 24
#define NSPLIT 64        // kmix tree splits (2 trees per block)
#define NZC 28           // complement-index capacity (actual = 26)

typedef unsigned long long u64x;

__device__ __forceinline__ u64x pk2(float lo, float hi) {
    u64x r; asm("mov.b64 %0, {%1, %2};" : "=l"(r) : "f"(lo), "f"(hi)); return r;
}
__device__ __forceinline__ void upk2(float& lo, float& hi, u64x v) {
    asm("mov.b64 {%0, %1}, %2;" : "=f"(lo), "=f"(hi) : "l"(v));
}
__device__ __forceinline__ u64x mul2_(u64x a, u64x b) {
    u64x d; asm("mul.rn.f32x2 %0, %1, %2;" : "=l"(d) : "l"(a), "l"(b)); return d;
}
__device__ __forceinline__ u64x fma2_(u64x a, u64x b, u64x c) {
    u64x d; asm("fma.rn.f32x2 %0, %1, %2, %3;" : "=l"(d) : "l"(a), "l"(b), "l"(c)); return d;
}
__device__ __forceinline__ u64x d2u(double v) { return (u64x)__double_as_longlong(v); }

// ---------------- scratch (__device__ globals; no allocation) ----------------
__device__ float g_LP[T_ * L_ * LPROW];            // softmaxed leaf probs, duplicated pairs
__device__ float g_attn[T_ * B_];                  // attention, TRANSPOSED [t][b]
__device__ float g_s[(size_t)TD_ * B_];            // softsign(z), TRANSPOSED [t*7+d][b]
__device__ float g_part[NSPLIT * C_ * B_];         // kmix partials, planar [ts][c][b]
__device__ float g_xT[(size_t)I_ * B_];            // x transposed [i][b]
__device__ int   g_cidx[TD_ * NZC];                // complement (zero-mask) indices

// ---------------- kernel 1: fused setup (leaf softmax | cidx | transpose) ---
// blocks [0,64): leaf softmax; [64,68): complement idx; [68,1092): x transpose
__global__ __launch_bounds__(256)
void setup_kernel(const float* __restrict__ leaf, const float* __restrict__ fm,
                  const float* __restrict__ x, float* __restrict__ lp,
                  int* __restrict__ cidx, float* __restrict__ xT) {
    __shared__ float tsh[32][33];
    int bid = blockIdx.x, tid = threadIdx.x;
    if (bid < 64) {
        int idx = bid * 256 + tid;                 // t*128 + l
        const float* in = leaf + (size_t)idx * C_;
        float v[C_];
        float m = -1e30f;
        #pragma unroll
        for (int c = 0; c < C_; c++) { v[c] = in[c]; m = fmaxf(m, v[c]); }
        float sum = 0.f;
        #pragma unroll
        for (int c = 0; c < C_; c++) { v[c] = expf(v[c] - m); sum += v[c]; }
        float inv = 1.0f / sum;
        float* o = lp + (size_t)idx * LPROW;
        #pragma unroll
        for (int c = 0; c < C_; c++) { float p = v[c] * inv; o[2*c] = p; o[2*c+1] = p; }
        o[20] = 0.f; o[21] = 0.f; o[22] = 0.f; o[23] = 0.f;
    } else if (bid < 68) {
        int n = (bid - 64) * 256 + tid;
        if (n < TD_) {
            int cnt = 0;
            for (int i = 0; i < I_; i++) {
                if (fm[(size_t)n * I_ + i] < 0.5f && cnt < NZC) cidx[n * NZC + cnt++] = i;
            }
            while (cnt < NZC) cidx[n * NZC + cnt++] = I_;   // sentinel -> zero row
        }
    } else {
        int flat = bid - 68;                       // 1024 transpose tiles
        int bx = (flat & 255) * 32, ix = (flat >> 8) * 32;
        int l = tid & 31, w = tid >> 5;
        #pragma unroll
        for (int r = 0; r < 32; r += 8)
            tsh[w + r][l] = x[(size_t)(bx + w + r) * I_ + ix + l];
        __syncthreads();
        #pragma unroll
        for (int r = 0; r < 32; r += 8)
            xT[(size_t)(ix + w + r) * B_ + bx + l] = tsh[l][w + r];
    }
}

// ---------------- kernel 2: MLP attention, register-tiled two-phase GEMM ----
// block: 32 b-rows, 256 threads (16 tm x 16 tn), grid 256.
// phase1: [32b x 64h x 128k], micro 2m x 4h -> relu -> As2[h][m]
// phase2: [32b x 128t x 64k], micro 2m x 8t -> +b2 -> softmax (16-lane groups)
#define A1S 36
#define B1S 68
#define A2S 36
#define B2S 132
#define SOS 34
#define ATTN_SMEM_FLOATS (8448 + 8704 + 4352)
__global__ __launch_bounds__(256, 2)
void attn_kernel(const float* __restrict__ x,  const float* __restrict__ W1,
                 const float* __restrict__ b1, const float* __restrict__ W2,
                 const float* __restrict__ b2, float* __restrict__ attn_out) {
    extern __shared__ float sma[];
    float* bufA = sma;                 // 8448: As1 [k=128][m=32] s36 ; later Bs2 [k=64][t=128] s132
    float* bufB = sma + 8448;          // 8704: Bs1 [k=128][h=64] s68 ; later As2 [h=64][m=32] s36
    float* sout = sma + 17152;         // 4352: [t=128][m=32] s34
    int tid = threadIdx.x;
    int b0 = blockIdx.x * 32;
    int tm = tid >> 4, tn = tid & 15;

    // stage As1 (x tile, k-major) and Bs1 (W1, k-major)
    for (int idx = tid; idx < 1024; idx += 256) {
        int m = idx >> 5, k4 = idx & 31;
        float4 v = *(const float4*)&x[(size_t)(b0 + m) * I_ + 4 * k4];
        bufA[(4 * k4 + 0) * A1S + m] = v.x;
        bufA[(4 * k4 + 1) * A1S + m] = v.y;
        bufA[(4 * k4 + 2) * A1S + m] = v.z;
        bufA[(4 * k4 + 3) * A1S + m] = v.w;
    }
    for (int idx = tid; idx < 2048; idx += 256) {
        int i = idx >> 4, h4 = idx & 15;
        float4 v = *(const float4*)&W1[(size_t)i * 64 + 4 * h4];
        *(float4*)&bufB[i * B1S + 4 * h4] = v;
    }
    __syncthreads();

    // phase 1 GEMM: acc[2m][4h]
    float acc[2][4];
    #pragma unroll
    for (int v = 0; v < 4; v++) {
        float bb1 = __ldg(&b1[tn * 4 + v]);
        acc[0][v] = bb1; acc[1][v] = bb1;
    }
    #pragma unroll 8
    for (int k = 0; k < 128; k++) {
        float2 a = *(const float2*)&bufA[k * A1S + tm * 2];
        float4 b = *(const float4*)&bufB[k * B1S + tn * 4];
        acc[0][0] = fmaf(a.x, b.x, acc[0][0]); acc[0][1] = fmaf(a.x, b.y, acc[0][1]);
        acc[0][2] = fmaf(a.x, b.z, acc[0][2]); acc[0][3] = fmaf(a.x, b.w, acc[0][3]);
        acc[1][0] = fmaf(a.y, b.x, acc[1][0]); acc[1][1] = fmaf(a.y, b.y, acc[1][1]);
        acc[1][2] = fmaf(a.y, b.z, acc[1][2]); acc[1][3] = fmaf(a.y, b.w, acc[1][3]);
    }
    __syncthreads();   // done with As1/Bs1 contents

    // relu -> As2[h][m] (in bufB); stage Bs2 (W2 k-major) into bufA
    #pragma unroll
    for (int v = 0; v < 4; v++) {
        bufB[(tn * 4 + v) * A2S + tm * 2 + 0] = fmaxf(acc[0][v], 0.f);
        bufB[(tn * 4 + v) * A2S + tm * 2 + 1] = fmaxf(acc[1][v], 0.f);
    }
    for (int idx = tid; idx < 2048; idx += 256) {
        int h = idx >> 5, t4 = idx & 31;
        float4 v = *(const float4*)&W2[(size_t)h * T_ + 4 * t4];
        *(float4*)&bufA[h * B2S + 4 * t4] = v;
    }
    __syncthreads();

    // phase 2 GEMM: acc2[2m][8t]
    float acc2[2][8];
    #pragma unroll
    for (int v = 0; v < 8; v++) {
        float bb2 = __ldg(&b2[tn * 8 + v]);
        acc2[0][v] = bb2; acc2[1][v] = bb2;
    }
    #pragma unroll 4
    for (int k = 0; k < 64; k++) {
        float2 a  = *(const float2*)&bufB[k * A2S + tm * 2];
        float4 c0 = *(const float4*)&bufA[k * B2S + tn * 8];
        float4 c1 = *(const float4*)&bufA[k * B2S + tn * 8 + 4];
        acc2[0][0] = fmaf(a.x, c0.x, acc2[0][0]); acc2[1][0] = fmaf(a.y, c0.x, acc2[1][0]);
        acc2[0][1] = fmaf(a.x, c0.y, acc2[0][1]); acc2[1][1] = fmaf(a.y, c0.y, acc2[1][1]);
        acc2[0][2] = fmaf(a.x, c0.z, acc2[0][2]); acc2[1][2] = fmaf(a.y, c0.z, acc2[1][2]);
        acc2[0][3] = fmaf(a.x, c0.w, acc2[0][3]); acc2[1][3] = fmaf(a.y, c0.w, acc2[1][3]);
        acc2[0][4] = fmaf(a.x, c1.x, acc2[0][4]); acc2[1][4] = fmaf(a.y, c1.x, acc2[1][4]);
        acc2[0][5] = fmaf(a.x, c1.y, acc2[0][5]); acc2[1][5] = fmaf(a.y, c1.y, acc2[1][5]);
        acc2[0][6] = fmaf(a.x, c1.z, acc2[0][6]); acc2[1][6] = fmaf(a.y, c1.z, acc2[1][6]);
        acc2[0][7] = fmaf(a.x, c1.w, acc2[0][7]); acc2[1][7] = fmaf(a.y, c1.w, acc2[1][7]);
    }

    // softmax over t: 16-thread groups (same tm; xor 1,2,4,8 stay in group)
    #pragma unroll
    for (int u = 0; u < 2; u++) {
        float mx = acc2[u][0];
        #pragma unroll
        for (int v = 1; v < 8; v++) mx = fmaxf(mx, acc2[u][v]);
        #pragma unroll
        for (int o = 8; o; o >>= 1) mx = fmaxf(mx, __shfl_xor_sync(0xffffffffu, mx, o));
        float sum = 0.f;
        #pragma unroll
        for (int v = 0; v < 8; v++) { acc2[u][v] = expf(acc2[u][v] - mx); sum += acc2[u][v]; }
        #pragma unroll
        for (int o = 8; o; o >>= 1) sum += __shfl_xor_sync(0xffffffffu, sum, o);
        float inv = 1.0f / sum;
        #pragma unroll
        for (int v = 0; v < 8; v++)
            sout[(tn * 8 + v) * SOS + tm * 2 + u] = acc2[u][v] * inv;
    }
    __syncthreads();

    // coalesced transposed store: attn_out[t][b]
    for (int i = tid; i < 128 * 32; i += 256) {
        int t = i >> 5, m = i & 31;
        attn_out[(size_t)t * B_ + b0 + m] = sout[t * SOS + m];
    }
}

// ---------------- kernel 3: z via complement sparsity + softsign ------------
#define KZS_SMEM_BYTES ((129 * 132 + 128) * 4)
__global__ __launch_bounds__(128)
void kz_sparse_kernel(const float* __restrict__ xT, const int* __restrict__ cidx,
                      const float* __restrict__ thr, float* __restrict__ s_out) {
    extern __shared__ float sms[];
    float* xs = sms;                 // [129][132]
    float* rs = sms + 129 * 132;     // [128]
    int tid = threadIdx.x, w = tid >> 5, lane = tid & 31;
    int b0 = blockIdx.x * 128, n0 = blockIdx.y * 128;

    for (int it = tid; it < 128 * 32; it += 128) {
        int i = it >> 5, c = it & 31;
        float4 v = *(const float4*)&xT[(size_t)i * B_ + b0 + c * 4];
        *(float4*)&xs[i * 132 + c * 4] = v;
    }
    xs[128 * 132 + tid] = 0.f;
    __syncthreads();

    {
        float s0 = 0.f, s1 = 0.f, s2 = 0.f, s3 = 0.f;
        for (int i = 0; i < I_; i += 4) {
            s0 += xs[(i + 0) * 132 + tid];
            s1 += xs[(i + 1) * 132 + tid];
            s2 += xs[(i + 2) * 132 + tid];
            s3 += xs[(i + 3) * 132 + tid];
        }
        rs[tid] = (s0 + s1) + (s2 + s3);
    }
    __syncthreads();

    const u64x NEG2 = 0xbf800000bf800000ULL;
    const u64x ONE2 = 0x3f8000003f800000ULL;

    for (int q = 0; q < 32; q++) {
        int n = n0 + w * 32 + q;
        const int* ci = cidx + n * NZC;
        double2 r2 = *(const double2*)&rs[lane * 4];
        u64x aE01 = d2u(r2.x), aO01 = 0;
        u64x aE23 = d2u(r2.y), aO23 = 0;
        #pragma unroll
        for (int j = 0; j < NZC; j += 2) {
            int i0 = __ldg(ci + j);
            int i1 = __ldg(ci + j + 1);
            double2 x0 = *(const double2*)&xs[i0 * 132 + lane * 4];
            double2 x1 = *(const double2*)&xs[i1 * 132 + lane * 4];
            aE01 = fma2_(d2u(x0.x), NEG2, aE01);
            aE23 = fma2_(d2u(x0.y), NEG2, aE23);
            aO01 = fma2_(d2u(x1.x), NEG2, aO01);
            aO23 = fma2_(d2u(x1.y), NEG2, aO23);
        }
        u64x a01 = fma2_(aO01, ONE2, aE01);
        u64x a23 = fma2_(aO23, ONE2, aE23);

        float th = __ldg(&thr[n]);
        float z0, z1, z2, z3;
        upk2(z0, z1, a01); upk2(z2, z3, a23);
        z0 -= th; z1 -= th; z2 -= th; z3 -= th;
        float4 o;
        o.x = fmaf(0.5f, __fdividef(z0, 1.0f + fabsf(z0)), 0.5f);
        o.y = fmaf(0.5f, __fdividef(z1, 1.0f + fabsf(z1)), 0.5f);
        o.z = fmaf(0.5f, __fdividef(z2, 1.0f + fabsf(z2)), 0.5f);
        o.w = fmaf(0.5f, __fdividef(z3, 1.0f + fabsf(z3)), 0.5f);
        *(float4*)&s_out[(size_t)n * B_ + b0 + lane * 4] = o;
    }
}

// ---------------- kernel 4: leaf mix, shared slab + software pipeline -------
#define KMIX_SMEM_FLOATS (2 * L_ * LPROW)     // double-buffered slab, 24KB
__global__ __launch_bounds__(128, 3)
void kmix_kernel(const float* __restrict__ s_in, const float* __restrict__ attn,
                 const float* __restrict__ lp, float* __restrict__ part) {
    extern __shared__ float smm[];
    int tid = threadIdx.x;
    int bbase = blockIdx.x * 512;
    int ts = blockIdx.y;
    int t0 = ts * 2;

    const u64x ONE2 = 0x3f8000003f800000ULL;
    const u64x NEG2 = 0xbf800000bf800000ULL;

    u64x acc[C_][2];
    #pragma unroll
    for (int c = 0; c < C_; c++) { acc[c][0] = 0; acc[c][1] = 0; }

    {
        const float4* src = (const float4*)(lp + (size_t)t0 * (L_ * LPROW));
        float4* dst = (float4*)smm;
        #pragma unroll
        for (int k = 0; k < 6; k++) dst[tid + 128 * k] = src[tid + 128 * k];
    }
    __syncthreads();

    #pragma unroll
    for (int tt = 0; tt < 2; tt++) {
        int t = t0 + tt;
        if (tt == 0) {
            const float4* src = (const float4*)(lp + (size_t)(t0 + 1) * (L_ * LPROW));
            float4* dst = (float4*)(smm + L_ * LPROW);
            #pragma unroll
            for (int k = 0; k < 6; k++) dst[tid + 128 * k] = src[tid + 128 * k];
        }
        const float* slab = smm + tt * (L_ * LPROW);

        u64x sv0[D_], mv0[D_], sv1[D_], mv1[D_];
        const float* sp = s_in + (size_t)(t * D_) * B_ + bbase + tid;
        #pragma unroll
        for (int d = 0; d < D_; d++) {
            const float* q = sp + (size_t)d * B_;
            sv0[d] = pk2(q[0],   q[128]);
            sv1[d] = pk2(q[256], q[384]);
            mv0[d] = fma2_(sv0[d], NEG2, ONE2);
            mv1[d] = fma2_(sv1[d], NEG2, ONE2);
        }
        const float* ap = attn + (size_t)t * B_ + bbase + tid;
        u64x a0 = pk2(ap[0],   ap[128]);
        u64x a1 = pk2(ap[256], ap[384]);

        u64x pl0[8], pl1[8];
        pl0[0] = sv0[0]; pl0[1] = mv0[0];
        pl1[0] = sv1[0]; pl1[1] = mv1[0];
        pl0[2] = mul2_(pl0[0], mv0[1]); pl0[3] = mul2_(pl0[1], mv0[1]);
        pl1[2] = mul2_(pl1[0], mv1[1]); pl1[3] = mul2_(pl1[1], mv1[1]);
        pl0[0] = mul2_(pl0[0], sv0[1]); pl0[1] = mul2_(pl0[1], sv0[1]);
        pl1[0] = mul2_(pl1[0], sv1[1]); pl1[1] = mul2_(pl1[1], sv1[1]);
        pl0[4] = mul2_(pl0[0], mv0[2]); pl0[5] = mul2_(pl0[1], mv0[2]);
        pl0[6] = mul2_(pl0[2], mv0[2]); pl0[7] = mul2_(pl0[3], mv0[2]);
        pl1[4] = mul2_(pl1[0], mv1[2]); pl1[5] = mul2_(pl1[1], mv1[2]);
        pl1[6] = mul2_(pl1[2], mv1[2]); pl1[7] = mul2_(pl1[3], mv1[2]);
        pl0[0] = mul2_(pl0[0], sv0[2]); pl0[1] = mul2_(pl0[1], sv0[2]);
        pl0[2] = mul2_(pl0[2], sv0[2]); pl0[3] = mul2_(pl0[3], sv0[2]);
        pl1[0] = mul2_(pl1[0], sv1[2]); pl1[1] = mul2_(pl1[1], sv1[2]);
        pl1[2] = mul2_(pl1[2], sv1[2]); pl1[3] = mul2_(pl1[3], sv1[2]);

        u64x t00 = mul2_(a0, sv0[3]), t01 = mul2_(a0, mv0[3]);
        u64x t10 = mul2_(a1, sv1[3]), t11 = mul2_(a1, mv1[3]);
        u64x ph40[4], ph41[4], f0[4], f1[4];
        ph40[0] = mul2_(t00, sv0[4]); ph40[1] = mul2_(t01, sv0[4]);
        ph40[2] = mul2_(t00, mv0[4]); ph40[3] = mul2_(t01, mv0[4]);
        ph41[0] = mul2_(t10, sv1[4]); ph41[1] = mul2_(t11, sv1[4]);
        ph41[2] = mul2_(t10, mv1[4]); ph41[3] = mul2_(t11, mv1[4]);
        f0[0] = mul2_(sv0[5], sv0[6]); f0[1] = mul2_(mv0[5], sv0[6]);
        f0[2] = mul2_(sv0[5], mv0[6]); f0[3] = mul2_(mv0[5], mv0[6]);
        f1[0] = mul2_(sv1[5], sv1[6]); f1[1] = mul2_(mv1[5], sv1[6]);
        f1[2] = mul2_(sv1[5], mv1[6]); f1[3] = mul2_(mv1[5], mv1[6]);

        double2 buf[2][5];
        buf[0][0] = *(const double2*)(slab);
        buf[0][1] = *(const double2*)(slab + 4);
        buf[0][2] = *(const double2*)(slab + 8);
        buf[0][3] = *(const double2*)(slab + 12);
        buf[0][4] = *(const double2*)(slab + 16);
        #pragma unroll
        for (int m = 0; m < 16; m++) {
            u64x pm0 = mul2_(ph40[m & 3], f0[m >> 2]);
            u64x pm1 = mul2_(ph41[m & 3], f1[m >> 2]);
            #pragma unroll
            for (int j = 0; j < 8; j++) {
                int l = m * 8 + j;
                int p = l & 1, np = p ^ 1;
                const float* Ln = slab + ((l + 1) & 127) * LPROW;
                buf[np][0] = *(const double2*)(Ln);
                buf[np][1] = *(const double2*)(Ln + 4);
                buf[np][2] = *(const double2*)(Ln + 8);
                buf[np][3] = *(const double2*)(Ln + 12);
                buf[np][4] = *(const double2*)(Ln + 16);
                u64x q0 = mul2_(pl0[j], pm0);
                u64x q1 = mul2_(pl1[j], pm1);
                acc[0][0] = fma2_(q0, d2u(buf[p][0].x), acc[0][0]);
                acc[0][1] = fma2_(q1, d2u(buf[p][0].x), acc[0][1]);
                acc[1][0] = fma2_(q0, d2u(buf[p][0].y), acc[1][0]);
                acc[1][1] = fma2_(q1, d2u(buf[p][0].y), acc[1][1]);
                acc[2][0] = fma2_(q0, d2u(buf[p][1].x), acc[2][0]);
                acc[2][1] = fma2_(q1, d2u(buf[p][1].x), acc[2][1]);
                acc[3][0] = fma2_(q0, d2u(buf[p][1].y), acc[3][0]);
                acc[3][1] = fma2_(q1, d2u(buf[p][1].y), acc[3][1]);
                acc[4][0] = fma2_(q0, d2u(buf[p][2].x), acc[4][0]);
                acc[4][1] = fma2_(q1, d2u(buf[p][2].x), acc[4][1]);
                acc[5][0] = fma2_(q0, d2u(buf[p][2].y), acc[5][0]);
                acc[5][1] = fma2_(q1, d2u(buf[p][2].y), acc[5][1]);
                acc[6][0] = fma2_(q0, d2u(buf[p][3].x), acc[6][0]);
                acc[6][1] = fma2_(q1, d2u(buf[p][3].x), acc[6][1]);
                acc[7][0] = fma2_(q0, d2u(buf[p][3].y), acc[7][0]);
                acc[7][1] = fma2_(q1, d2u(buf[p][3].y), acc[7][1]);
                acc[8][0] = fma2_(q0, d2u(buf[p][4].x), acc[8][0]);
                acc[8][1] = fma2_(q1, d2u(buf[p][4].x), acc[8][1]);
                acc[9][0] = fma2_(q0, d2u(buf[p][4].y), acc[9][0]);
                acc[9][1] = fma2_(q1, d2u(buf[p][4].y), acc[9][1]);
            }
        }
        __syncthreads();
    }

    #pragma unroll
    for (int c = 0; c < C_; c++) {
        float v0, v1, v2, v3;
        upk2(v0, v1, acc[c][0]);
        upk2(v2, v3, acc[c][1]);
        float* o = part + ((size_t)ts * C_ + c) * B_ + bbase + tid;
        o[0]   = v0;
        o[128] = v1;
        o[256] = v2;
        o[384] = v3;
    }
}

// ---------------- kernel 5: sum the NSPLIT planar partials ----------------
__global__ __launch_bounds__(256)
void reduce_kernel(const float* __restrict__ part, float* __restrict__ out) {
    int idx = blockIdx.x * blockDim.x + threadIdx.x;    // c*B + b
    if (idx >= B_ * C_) return;
    int c = idx >> 13;           // / B_
    int b = idx & (B_ - 1);
    float s = 0.f;
    #pragma unroll
    for (int k = 0; k < NSPLIT; k++)
        s += part[((size_t)k * C_ + c) * B_ + b];
    out[(size_t)b * C_ + c] = s;
}

// ---------------- launcher ----------------
extern "C" void kernel_launch(void* const* d_in, const int* in_sizes, int n_in,
                              void* d_out, int out_size) {
    const float* x    = (const float*)d_in[0];
    const float* fm   = (const float*)d_in[1];
    const float* thr  = (const float*)d_in[2];
    const float* leaf = (const float*)d_in[3];
    const float* W1   = (const float*)d_in[4];
    const float* b1   = (const float*)d_in[5];
    const float* W2   = (const float*)d_in[6];
    const float* b2   = (const float*)d_in[7];
    float* out = (float*)d_out;

    float *gLP, *gAt, *gS, *gP, *gXT;
    int* gCI;
    cudaGetSymbolAddress((void**)&gLP, g_LP);
    cudaGetSymbolAddress((void**)&gAt, g_attn);
    cudaGetSymbolAddress((void**)&gS,  g_s);
    cudaGetSymbolAddress((void**)&gP,  g_part);
    cudaGetSymbolAddress((void**)&gXT, g_xT);
    cudaGetSymbolAddress((void**)&gCI, g_cidx);

    cudaFuncSetAttribute(attn_kernel, cudaFuncAttributeMaxDynamicSharedMemorySize,
                         ATTN_SMEM_FLOATS * 4);
    cudaFuncSetAttribute(kz_sparse_kernel, cudaFuncAttributeMaxDynamicSharedMemorySize,
                         KZS_SMEM_BYTES);
    cudaFuncSetAttribute(kmix_kernel, cudaFuncAttributeMaxDynamicSharedMemorySize,
                         KMIX_SMEM_FLOATS * 4);
    (void)in_sizes; (void)n_in; (void)out_size;

    setup_kernel<<<68 + 1024, 256>>>(leaf, fm, x, gLP, gCI, gXT);
    attn_kernel<<<B_ / 32, 256, ATTN_SMEM_FLOATS * 4>>>(x, W1, b1, W2, b2, gAt);
    kz_sparse_kernel<<<dim3(B_ / 128, TD_ / 128), 128, KZS_SMEM_BYTES>>>(gXT, gCI, thr, gS);
    kmix_kernel<<<dim3(B_ / 512, NSPLIT), 128, KMIX_SMEM_FLOATS * 4>>>(gS, gAt, gLP, gP);
    reduce_kernel<<<(B_ * C_ + 255) / 256, 256>>>(gP, out);
}